// round 10
// baseline (speedup 1.0000x reference)
#include <cuda_runtime.h>
#include <cuda_bf16.h>
#include <cstdint>

// ---------------------------------------------------------------------------
// WaveFDTD2D, temporal blocking K=4, 128 persistent CTAs x 512 threads.
// R8 base (strided row ownership {ty, ty+4, ty+8}; m/o/cf register-resident;
// 2 ping-pong SMEM field images; neighbor-only monotonic-counter sync) plus:
//  - substeps batch ALL SMEM loads (u/d/lf/rg, 10 floats/row) before compute
//    so LDS latency is paid once per substep, not once per row
//  - all threads spin on neighbor counters directly (no tid0+bar broadcast)
// ---------------------------------------------------------------------------

#define NX      512
#define NZ      512
#define NSTEPS  512
#define NREC    128
#define KST     4
#define NBLK    (NSTEPS / KST)     // 128
#define NCTA    128
#define NTHR    512
#define RROWS   4
#define EXT     12                 // SMEM image rows 0..11
#define SROW    520
#define BUF     (EXT * SROW)
#define SMEM_FLOATS (2 * BUF)      // S0, S1
#define SMEM_BYTES  (SMEM_FLOATS * 4)
#define PAD     32

__device__ __align__(16) float g_P[2][NX * NZ];
__device__ __align__(16) float g_Q[2][NX * NZ];
__device__ unsigned long long g_done[NCTA * PAD];   // monotonic, never reset

static __device__ __forceinline__ void signal_done(int bid) {
    asm volatile("red.add.release.gpu.u64 [%0], 1;"
                 :: "l"(&g_done[bid * PAD]) : "memory");
}

// Every thread spins until both neighbor counters reach tgt.
static __device__ __forceinline__ void wait_neighbors_all(int bid, unsigned long long tgt) {
    const unsigned long long* lo =
        (bid > 0) ? &g_done[(bid - 1) * PAD] : nullptr;
    const unsigned long long* hi =
        (bid < NCTA - 1) ? &g_done[(bid + 1) * PAD] : nullptr;
    bool need_lo = (lo != nullptr), need_hi = (hi != nullptr);
    while (need_lo || need_hi) {
        unsigned long long a = tgt, b = tgt;
        if (need_lo)
            asm volatile("ld.acquire.gpu.u64 %0, [%1];" : "=l"(a) : "l"(lo) : "memory");
        if (need_hi)
            asm volatile("ld.acquire.gpu.u64 %0, [%1];" : "=l"(b) : "l"(hi) : "memory");
        if (a >= tgt) need_lo = false;
        if (b >= tgt) need_hi = false;
    }
}

// One substep over rows [LO,HI]; thread's rows are {ty, ty+4, ty+8}.
// Phase 1: all SMEM loads (u/d/lf/rg). Phase 2: compute from register state.
template<int LO, int HI, bool STORE>
static __device__ __forceinline__ void substep(
    const float* __restrict__ Scur, float* __restrict__ Snext,
    float4 (&m)[3], float4 (&o)[3], const float4 (&cf)[3],
    int clo, int chi, int g0, int tx, int ty,
    int sx, int sz, const float* __restrict__ source, int t,
    float* __restrict__ gdst)
{
    const float INV  = 0.01f;    // 1/(dx*dz)
    const float DT2f = 1.0e-6f;  // dt^2
    const int colbase = 4 + tx * 4;

    float4 u[3], d[3];
    float  lf[3], rg[3];
    bool   valid[3];

    // ---- phase 1: batch all SMEM loads ----
    #pragma unroll
    for (int k = 0; k < 3; ++k) {
        const int i = ty + 4 * k;
        valid[k] = (i >= LO) && (i <= HI) && (i >= clo) && (i <= chi);
        if (valid[k]) {
            const int base = i * SROW + colbase;
            u[k]  = *reinterpret_cast<const float4*>(Scur + base - SROW);
            d[k]  = *reinterpret_cast<const float4*>(Scur + base + SROW);
            lf[k] = Scur[base - 1];
            rg[k] = Scur[base + 4];
        }
    }

    // ---- phase 2: compute + store ----
    #pragma unroll
    for (int k = 0; k < 3; ++k) {
        if (!valid[k]) continue;
        const int i = ty + 4 * k;
        const int base = i * SROW + colbase;
        float4 nw; float lap;
        lap  = ((((u[k].x + d[k].x) + lf[k])  + m[k].y) - 4.0f * m[k].x) * INV;
        nw.x = (2.0f * m[k].x - o[k].x) + cf[k].x * lap;
        lap  = ((((u[k].y + d[k].y) + m[k].x) + m[k].z) - 4.0f * m[k].y) * INV;
        nw.y = (2.0f * m[k].y - o[k].y) + cf[k].y * lap;
        lap  = ((((u[k].z + d[k].z) + m[k].y) + m[k].w) - 4.0f * m[k].z) * INV;
        nw.z = (2.0f * m[k].z - o[k].z) + cf[k].z * lap;
        lap  = ((((u[k].w + d[k].w) + m[k].z) + rg[k])  - 4.0f * m[k].w) * INV;
        nw.w = (2.0f * m[k].w - o[k].w) + cf[k].w * lap;
        const int g = g0 - 4 + i;
        if (g == sx && (sz >> 2) == tx) {
            const float sadd = __ldg(source + t) * DT2f;
            const int lane = sz & 3;
            nw.x += (lane == 0) ? sadd : 0.0f;
            nw.y += (lane == 1) ? sadd : 0.0f;
            nw.z += (lane == 2) ? sadd : 0.0f;
            nw.w += (lane == 3) ? sadd : 0.0f;
        }
        *reinterpret_cast<float4*>(Snext + base) = nw;
        if (STORE && k == 1) {
            __stcg(reinterpret_cast<float4*>(gdst + (size_t)g * NZ + tx * 4), nw);
        }
        o[k] = m[k];
        m[k] = nw;
    }
}

__global__ void __launch_bounds__(NTHR, 1)
wave_fdtd_reg_kernel(const float* __restrict__ vel,
                     const float* __restrict__ source,
                     const int*   __restrict__ p_srcx,
                     const int*   __restrict__ p_srcz,
                     const int*   __restrict__ rec_x,
                     const int*   __restrict__ rec_z,
                     float*       __restrict__ out)
{
    extern __shared__ float sm[];
    __shared__ unsigned long long sm_base;
    float* S0 = sm;           // p_n at block entry / p_{n+4} at exit
    float* S1 = sm + BUF;

    const int tid = threadIdx.x;
    const int bid = blockIdx.x;
    const int g0  = bid * RROWS;
    const int tx  = tid & 127;
    const int ty  = tid >> 7;    // 0..3 -> rows {ty, ty+4, ty+8}
    const int colbase = 4 + tx * 4;

    const int sx = p_srcx[0];
    const int sz = p_srcz[0];

    const int clo = 4 - g0;        // min valid SMEM row
    const int chi = 515 - g0;      // max valid SMEM row

    int my_rx = -1, my_rz = 0;
    if (tid < NREC) { my_rx = __ldg(rec_x + tid); my_rz = __ldg(rec_z + tid); }
    const bool my_rec = (my_rx >= 0) && ((my_rx >> 2) == bid);
    const int  rec_off = my_rec ? ((4 + (my_rx & 3)) * SROW + 4 + my_rz) : 0;

    // ---- zero SMEM; read own counter base ----
    for (int i = tid; i < SMEM_FLOATS; i += NTHR) sm[i] = 0.0f;
    if (tid == 0) sm_base = g_done[bid * PAD];
    __syncthreads();
    const unsigned long long base = sm_base;

    // ---- register state init ----
    const float DT2f = 1.0e-6f;
    float4 m[3], o[3], cf[3];
    #pragma unroll
    for (int k = 0; k < 3; ++k) {
        m[k] = make_float4(0.f, 0.f, 0.f, 0.f);
        o[k] = make_float4(0.f, 0.f, 0.f, 0.f);
        const int i = ty + 4 * k;
        const int g = g0 - 4 + i;
        if ((unsigned)g < (unsigned)NX) {
            const float4 v = __ldg(reinterpret_cast<const float4*>(
                                   vel + (size_t)g * NZ + tx * 4));
            cf[k] = make_float4(v.x * v.x * DT2f, v.y * v.y * DT2f,
                                v.z * v.z * DT2f, v.w * v.w * DT2f);
        } else {
            cf[k] = make_float4(0.f, 0.f, 0.f, 0.f);
        }
    }

    // ---- zero OWN rows of global pair 0 (stale from prior replay) ----
    {
        const float4 z = make_float4(0.f, 0.f, 0.f, 0.f);
        for (int idx = tid; idx < RROWS * 128; idx += NTHR) {
            const int r = idx >> 7, c = idx & 127;
            const size_t off = (size_t)(g0 + r) * NZ + c * 4;
            __stcg(reinterpret_cast<float4*>(g_P[0] + off), z);
            __stcg(reinterpret_cast<float4*>(g_Q[0] + off), z);
        }
    }
    __syncthreads();
    if (tid == 0) signal_done(bid);   // counter -> base+1

    for (int b = 0; b < NBLK; ++b) {
        // ---- every thread spins on neighbor counters (no broadcast bar) ----
        wait_neighbors_all(bid, base + 1 + (unsigned long long)b);

        const int pb = b & 1;
        const float* gp = g_P[pb];
        const float* gq = g_Q[pb];

        // ---- halo refresh: rows outside [4,7] reload m (and o) ----
        #pragma unroll
        for (int k = 0; k < 3; k += 2) {       // k=0 (rows 0..3), k=2 (rows 8..11)
            const int i = ty + 4 * k;
            const int g = g0 - 4 + i;
            if ((unsigned)g < (unsigned)NX) {
                const float4 v = __ldcg(reinterpret_cast<const float4*>(
                                        gp + (size_t)g * NZ + tx * 4));
                if (i == 3 || i == 8) {
                    o[k] = m[k];               // p_{n-1} computed here at prev s3
                } else if (i == 1 || i == 2 || i == 9 || i == 10) {
                    o[k] = __ldcg(reinterpret_cast<const float4*>(
                                  gq + (size_t)g * NZ + tx * 4));
                }
                m[k] = v;
                *reinterpret_cast<float4*>(S0 + i * SROW + colbase) = v;
            }
        }
        __syncthreads();

        const int t0 = b * KST;
        float* gpo = g_P[pb ^ 1];
        float* gqo = g_Q[pb ^ 1];

        // s1: p_{n+1}, rows [1,10], S0 -> S1
        substep<1, 10, false>(S0, S1, m, o, cf, clo, chi, g0, tx, ty,
                              sx, sz, source, t0, nullptr);
        __syncthreads();
        if (my_rec) out[(size_t)tid * NSTEPS + t0] = S1[rec_off];

        // s2: p_{n+2}, rows [2,9], S1 -> S0
        substep<2, 9, false>(S1, S0, m, o, cf, clo, chi, g0, tx, ty,
                             sx, sz, source, t0 + 1, nullptr);
        __syncthreads();
        if (my_rec) out[(size_t)tid * NSTEPS + t0 + 1] = S0[rec_off];

        // s3: p_{n+3}, rows [3,8], S0 -> S1; own rows -> Q[pb^1]
        substep<3, 8, true>(S0, S1, m, o, cf, clo, chi, g0, tx, ty,
                            sx, sz, source, t0 + 2, gqo);
        __syncthreads();
        if (my_rec) out[(size_t)tid * NSTEPS + t0 + 2] = S1[rec_off];

        // s4: p_{n+4}, rows [4,7], S1 -> S0; own rows -> P[pb^1]
        substep<4, 7, true>(S1, S0, m, o, cf, clo, chi, g0, tx, ty,
                            sx, sz, source, t0 + 3, gpo);
        __syncthreads();
        if (my_rec) out[(size_t)tid * NSTEPS + t0 + 3] = S0[rec_off];

        if (tid == 0) signal_done(bid);   // counter -> base+2+b
    }
}

extern "C" void kernel_launch(void* const* d_in, const int* in_sizes, int n_in,
                              void* d_out, int out_size)
{
    const float* vel    = (const float*)d_in[0];
    const float* source = (const float*)d_in[1];
    const int*   srcx   = (const int*)d_in[2];
    const int*   srcz   = (const int*)d_in[3];
    const int*   rec_x  = (const int*)d_in[4];
    const int*   rec_z  = (const int*)d_in[5];
    float* out = (float*)d_out;

    cudaFuncSetAttribute(wave_fdtd_reg_kernel,
                         cudaFuncAttributeMaxDynamicSharedMemorySize, SMEM_BYTES);
    wave_fdtd_reg_kernel<<<NCTA, NTHR, SMEM_BYTES>>>(
        vel, source, srcx, srcz, rec_x, rec_z, out);
}

// round 11
// speedup vs baseline: 1.2418x; 1.2418x over previous
#include <cuda_runtime.h>
#include <cuda_bf16.h>
#include <cstdint>

// ---------------------------------------------------------------------------
// WaveFDTD2D, temporal blocking K=4, 128 persistent CTAs x 512 threads.
// R8 base: strided row ownership {ty, ty+4, ty+8}; m/o/cf register-resident;
// 2 ping-pong SMEM field images; neighbor-only monotonic-counter sync;
// per-row interleaved loads (NO batching -- batching spills, proven twice).
// R11 delta: left/right column neighbors come from warp shuffles of the
// adjacent lane's register state instead of scalar LDS (boundary lanes use a
// predicated SMEM fallback; grid edges use the zero pad).
// ---------------------------------------------------------------------------

#define NX      512
#define NZ      512
#define NSTEPS  512
#define NREC    128
#define KST     4
#define NBLK    (NSTEPS / KST)     // 128
#define NCTA    128
#define NTHR    512
#define RROWS   4
#define EXT     12                 // SMEM image rows 0..11
#define SROW    520
#define BUF     (EXT * SROW)
#define SMEM_FLOATS (2 * BUF)      // S0, S1
#define SMEM_BYTES  (SMEM_FLOATS * 4)
#define PAD     32

__device__ __align__(16) float g_P[2][NX * NZ];
__device__ __align__(16) float g_Q[2][NX * NZ];
__device__ unsigned long long g_done[NCTA * PAD];   // monotonic, never reset

static __device__ __forceinline__ void signal_done(int bid) {
    asm volatile("red.add.release.gpu.u64 [%0], 1;"
                 :: "l"(&g_done[bid * PAD]) : "memory");
}

static __device__ __forceinline__ void wait_neighbors(int bid, unsigned long long tgt) {
    const unsigned long long* lo =
        (bid > 0) ? &g_done[(bid - 1) * PAD] : nullptr;
    const unsigned long long* hi =
        (bid < NCTA - 1) ? &g_done[(bid + 1) * PAD] : nullptr;
    bool need_lo = (lo != nullptr), need_hi = (hi != nullptr);
    while (need_lo || need_hi) {
        unsigned long long a = tgt, b = tgt;
        if (need_lo)
            asm volatile("ld.acquire.gpu.u64 %0, [%1];" : "=l"(a) : "l"(lo) : "memory");
        if (need_hi)
            asm volatile("ld.acquire.gpu.u64 %0, [%1];" : "=l"(b) : "l"(hi) : "memory");
        if (a >= tgt) need_lo = false;
        if (b >= tgt) need_hi = false;
    }
}

// One substep over rows [LO,HI]; thread's rows are {ty, ty+4, ty+8}.
// u/d from SMEM; lf/rg from warp shuffle of adjacent lane's m[k]
// (boundary lanes: predicated SMEM scalar; tx 0/127: zero pad).
template<int LO, int HI, bool STORE>
static __device__ __forceinline__ void substep(
    const float* __restrict__ Scur, float* __restrict__ Snext,
    float4 (&m)[3], float4 (&o)[3], const float4 (&cf)[3],
    int clo, int chi, int g0, int tx, int ty, unsigned lane,
    int sx, int sz, const float* __restrict__ source, int t,
    float* __restrict__ gdst)
{
    const float INV  = 0.01f;    // 1/(dx*dz)
    const float DT2f = 1.0e-6f;  // dt^2
    const int colbase = 4 + tx * 4;

    #pragma unroll
    for (int k = 0; k < 3; ++k) {
        const int i = ty + 4 * k;
        const bool valid = (i >= LO) && (i <= HI) && (i >= clo) && (i <= chi);
        if (!valid) continue;    // uniform across the warp (same ty)
        const int base = i * SROW + colbase;

        // boundary-lane SMEM fallbacks (rare lanes only)
        float lfs = 0.0f, rgs = 0.0f;
        if (lane == 0 && tx != 0)    lfs = Scur[base - 1];
        if (lane == 31 && tx != 127) rgs = Scur[base + 4];

        float lf = __shfl_up_sync(0xFFFFFFFFu, m[k].w, 1);
        float rg = __shfl_down_sync(0xFFFFFFFFu, m[k].x, 1);
        if (lane == 0)  lf = lfs;
        if (lane == 31) rg = rgs;

        const float4 u = *reinterpret_cast<const float4*>(Scur + base - SROW);
        const float4 d = *reinterpret_cast<const float4*>(Scur + base + SROW);

        float4 nw; float lap;
        lap  = ((((u.x + d.x) + lf)     + m[k].y) - 4.0f * m[k].x) * INV;
        nw.x = (2.0f * m[k].x - o[k].x) + cf[k].x * lap;
        lap  = ((((u.y + d.y) + m[k].x) + m[k].z) - 4.0f * m[k].y) * INV;
        nw.y = (2.0f * m[k].y - o[k].y) + cf[k].y * lap;
        lap  = ((((u.z + d.z) + m[k].y) + m[k].w) - 4.0f * m[k].z) * INV;
        nw.z = (2.0f * m[k].z - o[k].z) + cf[k].z * lap;
        lap  = ((((u.w + d.w) + m[k].z) + rg)     - 4.0f * m[k].w) * INV;
        nw.w = (2.0f * m[k].w - o[k].w) + cf[k].w * lap;

        const int g = g0 - 4 + i;
        if (g == sx && (sz >> 2) == tx) {
            const float sadd = __ldg(source + t) * DT2f;
            const int sl = sz & 3;
            nw.x += (sl == 0) ? sadd : 0.0f;
            nw.y += (sl == 1) ? sadd : 0.0f;
            nw.z += (sl == 2) ? sadd : 0.0f;
            nw.w += (sl == 3) ? sadd : 0.0f;
        }
        *reinterpret_cast<float4*>(Snext + base) = nw;
        if (STORE && k == 1) {
            __stcg(reinterpret_cast<float4*>(gdst + (size_t)g * NZ + tx * 4), nw);
        }
        o[k] = m[k];
        m[k] = nw;
    }
}

__global__ void __launch_bounds__(NTHR, 1)
wave_fdtd_reg_kernel(const float* __restrict__ vel,
                     const float* __restrict__ source,
                     const int*   __restrict__ p_srcx,
                     const int*   __restrict__ p_srcz,
                     const int*   __restrict__ rec_x,
                     const int*   __restrict__ rec_z,
                     float*       __restrict__ out)
{
    extern __shared__ float sm[];
    __shared__ unsigned long long sm_base;
    float* S0 = sm;           // p_n at block entry / p_{n+4} at exit
    float* S1 = sm + BUF;

    const int tid = threadIdx.x;
    const int bid = blockIdx.x;
    const int g0  = bid * RROWS;
    const int tx  = tid & 127;
    const int ty  = tid >> 7;            // 0..3 -> rows {ty, ty+4, ty+8}
    const unsigned lane = tx & 31;       // == tid%32
    const int colbase = 4 + tx * 4;

    const int sx = p_srcx[0];
    const int sz = p_srcz[0];

    const int clo = 4 - g0;        // min valid SMEM row
    const int chi = 515 - g0;      // max valid SMEM row

    int my_rx = -1, my_rz = 0;
    if (tid < NREC) { my_rx = __ldg(rec_x + tid); my_rz = __ldg(rec_z + tid); }
    const bool my_rec = (my_rx >= 0) && ((my_rx >> 2) == bid);
    const int  rec_off = my_rec ? ((4 + (my_rx & 3)) * SROW + 4 + my_rz) : 0;

    // ---- zero SMEM; read own counter base ----
    for (int i = tid; i < SMEM_FLOATS; i += NTHR) sm[i] = 0.0f;
    if (tid == 0) sm_base = g_done[bid * PAD];
    __syncthreads();
    const unsigned long long base = sm_base;

    // ---- register state init ----
    const float DT2f = 1.0e-6f;
    float4 m[3], o[3], cf[3];
    #pragma unroll
    for (int k = 0; k < 3; ++k) {
        m[k] = make_float4(0.f, 0.f, 0.f, 0.f);
        o[k] = make_float4(0.f, 0.f, 0.f, 0.f);
        const int i = ty + 4 * k;
        const int g = g0 - 4 + i;
        if ((unsigned)g < (unsigned)NX) {
            const float4 v = __ldg(reinterpret_cast<const float4*>(
                                   vel + (size_t)g * NZ + tx * 4));
            cf[k] = make_float4(v.x * v.x * DT2f, v.y * v.y * DT2f,
                                v.z * v.z * DT2f, v.w * v.w * DT2f);
        } else {
            cf[k] = make_float4(0.f, 0.f, 0.f, 0.f);
        }
    }

    // ---- zero OWN rows of global pair 0 (stale from prior replay) ----
    {
        const float4 z = make_float4(0.f, 0.f, 0.f, 0.f);
        for (int idx = tid; idx < RROWS * 128; idx += NTHR) {
            const int r = idx >> 7, c = idx & 127;
            const size_t off = (size_t)(g0 + r) * NZ + c * 4;
            __stcg(reinterpret_cast<float4*>(g_P[0] + off), z);
            __stcg(reinterpret_cast<float4*>(g_Q[0] + off), z);
        }
    }
    __syncthreads();
    if (tid == 0) signal_done(bid);   // counter -> base+1

    for (int b = 0; b < NBLK; ++b) {
        if (tid == 0)
            wait_neighbors(bid, base + 1 + (unsigned long long)b);
        __syncthreads();

        const int pb = b & 1;
        const float* gp = g_P[pb];
        const float* gq = g_Q[pb];

        // ---- halo refresh: rows outside [4,7] reload m (and o) ----
        #pragma unroll
        for (int k = 0; k < 3; k += 2) {       // k=0 (rows 0..3), k=2 (rows 8..11)
            const int i = ty + 4 * k;
            const int g = g0 - 4 + i;
            if ((unsigned)g < (unsigned)NX) {
                const float4 v = __ldcg(reinterpret_cast<const float4*>(
                                        gp + (size_t)g * NZ + tx * 4));
                if (i == 3 || i == 8) {
                    o[k] = m[k];               // p_{n-1} computed here at prev s3
                } else if (i == 1 || i == 2 || i == 9 || i == 10) {
                    o[k] = __ldcg(reinterpret_cast<const float4*>(
                                  gq + (size_t)g * NZ + tx * 4));
                }
                m[k] = v;
                *reinterpret_cast<float4*>(S0 + i * SROW + colbase) = v;
            }
        }
        __syncthreads();

        const int t0 = b * KST;
        float* gpo = g_P[pb ^ 1];
        float* gqo = g_Q[pb ^ 1];

        // s1: p_{n+1}, rows [1,10], S0 -> S1
        substep<1, 10, false>(S0, S1, m, o, cf, clo, chi, g0, tx, ty, lane,
                              sx, sz, source, t0, nullptr);
        __syncthreads();
        if (my_rec) out[(size_t)tid * NSTEPS + t0] = S1[rec_off];

        // s2: p_{n+2}, rows [2,9], S1 -> S0
        substep<2, 9, false>(S1, S0, m, o, cf, clo, chi, g0, tx, ty, lane,
                             sx, sz, source, t0 + 1, nullptr);
        __syncthreads();
        if (my_rec) out[(size_t)tid * NSTEPS + t0 + 1] = S0[rec_off];

        // s3: p_{n+3}, rows [3,8], S0 -> S1; own rows -> Q[pb^1]
        substep<3, 8, true>(S0, S1, m, o, cf, clo, chi, g0, tx, ty, lane,
                            sx, sz, source, t0 + 2, gqo);
        __syncthreads();
        if (my_rec) out[(size_t)tid * NSTEPS + t0 + 2] = S1[rec_off];

        // s4: p_{n+4}, rows [4,7], S1 -> S0; own rows -> P[pb^1]
        substep<4, 7, true>(S1, S0, m, o, cf, clo, chi, g0, tx, ty, lane,
                            sx, sz, source, t0 + 3, gpo);
        __syncthreads();
        if (my_rec) out[(size_t)tid * NSTEPS + t0 + 3] = S0[rec_off];

        if (tid == 0) signal_done(bid);   // counter -> base+2+b
    }
}

extern "C" void kernel_launch(void* const* d_in, const int* in_sizes, int n_in,
                              void* d_out, int out_size)
{
    const float* vel    = (const float*)d_in[0];
    const float* source = (const float*)d_in[1];
    const int*   srcx   = (const int*)d_in[2];
    const int*   srcz   = (const int*)d_in[3];
    const int*   rec_x  = (const int*)d_in[4];
    const int*   rec_z  = (const int*)d_in[5];
    float* out = (float*)d_out;

    cudaFuncSetAttribute(wave_fdtd_reg_kernel,
                         cudaFuncAttributeMaxDynamicSharedMemorySize, SMEM_BYTES);
    wave_fdtd_reg_kernel<<<NCTA, NTHR, SMEM_BYTES>>>(
        vel, source, srcx, srcz, rec_x, rec_z, out);
}

// round 12
// speedup vs baseline: 1.3600x; 1.0952x over previous
#include <cuda_runtime.h>
#include <cuda_bf16.h>
#include <cstdint>

// ---------------------------------------------------------------------------
// WaveFDTD2D, temporal blocking K=4, 128 persistent CTAs x 768 threads.
// Thread (tx,ty), ty in 0..5, owns 2 rows {ty, ty+6} -> 24 state floats
// (m/o/cf), higher occupancy (24 warps/SM) to hide LDS/sync latency.
// Ping-pong SMEM field images; halo-only global traffic; neighbor-only
// monotonic-counter sync; interleaved per-row loads (batching spills: proven).
// ---------------------------------------------------------------------------

#define NX      512
#define NZ      512
#define NSTEPS  512
#define NREC    128
#define KST     4
#define NBLK    (NSTEPS / KST)     // 128
#define NCTA    128
#define NTHR    768
#define RROWS   4
#define EXT     12                 // SMEM image rows 0..11
#define SROW    520
#define BUF     (EXT * SROW)
#define SMEM_FLOATS (2 * BUF)      // S0, S1
#define SMEM_BYTES  (SMEM_FLOATS * 4)
#define PAD     32

__device__ __align__(16) float g_P[2][NX * NZ];
__device__ __align__(16) float g_Q[2][NX * NZ];
__device__ unsigned long long g_done[NCTA * PAD];   // monotonic, never reset

static __device__ __forceinline__ void signal_done(int bid) {
    asm volatile("red.add.release.gpu.u64 [%0], 1;"
                 :: "l"(&g_done[bid * PAD]) : "memory");
}

static __device__ __forceinline__ void wait_neighbors(int bid, unsigned long long tgt) {
    const unsigned long long* lo =
        (bid > 0) ? &g_done[(bid - 1) * PAD] : nullptr;
    const unsigned long long* hi =
        (bid < NCTA - 1) ? &g_done[(bid + 1) * PAD] : nullptr;
    bool need_lo = (lo != nullptr), need_hi = (hi != nullptr);
    while (need_lo || need_hi) {
        unsigned long long a = tgt, b = tgt;
        if (need_lo)
            asm volatile("ld.acquire.gpu.u64 %0, [%1];" : "=l"(a) : "l"(lo) : "memory");
        if (need_hi)
            asm volatile("ld.acquire.gpu.u64 %0, [%1];" : "=l"(b) : "l"(hi) : "memory");
        if (a >= tgt) need_lo = false;
        if (b >= tgt) need_hi = false;
    }
}

// Compute one row (4 cells). Updates m/o in place.
static __device__ __forceinline__ void row_update(
    const float* __restrict__ Scur, float* __restrict__ Snext,
    float4& m, float4& o, const float4 cf,
    int i, int g0, int tx,
    int sx, int sz, const float* __restrict__ source, int t,
    bool do_store, float* __restrict__ gdst)
{
    const float INV  = 0.01f;    // 1/(dx*dz)
    const float DT2f = 1.0e-6f;  // dt^2
    const int base = i * SROW + 4 + tx * 4;

    const float4 u  = *reinterpret_cast<const float4*>(Scur + base - SROW);
    const float4 d  = *reinterpret_cast<const float4*>(Scur + base + SROW);
    const float  lf = Scur[base - 1];
    const float  rg = Scur[base + 4];

    float4 nw; float lap;
    lap  = ((((u.x + d.x) + lf)  + m.y) - 4.0f * m.x) * INV;
    nw.x = (2.0f * m.x - o.x) + cf.x * lap;
    lap  = ((((u.y + d.y) + m.x) + m.z) - 4.0f * m.y) * INV;
    nw.y = (2.0f * m.y - o.y) + cf.y * lap;
    lap  = ((((u.z + d.z) + m.y) + m.w) - 4.0f * m.z) * INV;
    nw.z = (2.0f * m.z - o.z) + cf.z * lap;
    lap  = ((((u.w + d.w) + m.z) + rg)  - 4.0f * m.w) * INV;
    nw.w = (2.0f * m.w - o.w) + cf.w * lap;

    const int g = g0 - 4 + i;
    if (g == sx && (sz >> 2) == tx) {
        const float sadd = __ldg(source + t) * DT2f;
        const int sl = sz & 3;
        nw.x += (sl == 0) ? sadd : 0.0f;
        nw.y += (sl == 1) ? sadd : 0.0f;
        nw.z += (sl == 2) ? sadd : 0.0f;
        nw.w += (sl == 3) ? sadd : 0.0f;
    }
    *reinterpret_cast<float4*>(Snext + base) = nw;
    if (do_store) {
        __stcg(reinterpret_cast<float4*>(gdst + (size_t)g * NZ + tx * 4), nw);
    }
    o = m;
    m = nw;
}

// One substep over rows [LO,HI]; thread's rows are {ty, ty+6}.
// Slot 0 (row ty <= 5): only LO + low-edge clamp matter.
// Slot 1 (row ty+6 >= 6): only HI + high-edge clamp matter.
template<int LO, int HI, bool STORE>
static __device__ __forceinline__ void substep(
    const float* __restrict__ Scur, float* __restrict__ Snext,
    float4& m0, float4& o0, const float4 cf0,
    float4& m1, float4& o1, const float4 cf1,
    int clo, int chi, int g0, int tx, int ty,
    int sx, int sz, const float* __restrict__ source, int t,
    float* __restrict__ gdst)
{
    const int r0 = ty;        // 0..5
    const int r1 = ty + 6;    // 6..11
    if (r0 >= LO && r0 >= clo) {
        row_update(Scur, Snext, m0, o0, cf0, r0, g0, tx, sx, sz, source, t,
                   STORE && (r0 >= 4), gdst);     // r0<=5<=7 always
    }
    if (r1 <= HI && r1 <= chi) {
        row_update(Scur, Snext, m1, o1, cf1, r1, g0, tx, sx, sz, source, t,
                   STORE && (r1 <= 7), gdst);     // r1>=6>=4 always
    }
}

__global__ void __launch_bounds__(NTHR, 1)
wave_fdtd_reg_kernel(const float* __restrict__ vel,
                     const float* __restrict__ source,
                     const int*   __restrict__ p_srcx,
                     const int*   __restrict__ p_srcz,
                     const int*   __restrict__ rec_x,
                     const int*   __restrict__ rec_z,
                     float*       __restrict__ out)
{
    extern __shared__ float sm[];
    __shared__ unsigned long long sm_base;
    float* S0 = sm;           // p_n at block entry / p_{n+4} at exit
    float* S1 = sm + BUF;

    const int tid = threadIdx.x;
    const int bid = blockIdx.x;
    const int g0  = bid * RROWS;
    const int tx  = tid & 127;
    const int ty  = tid >> 7;    // 0..5 -> rows {ty, ty+6}
    const int colbase = 4 + tx * 4;

    const int sx = p_srcx[0];
    const int sz = p_srcz[0];

    const int clo = 4 - g0;        // min valid SMEM row (interior <= 0)
    const int chi = 515 - g0;      // max valid SMEM row (interior >= 11)

    int my_rx = -1, my_rz = 0;
    if (tid < NREC) { my_rx = __ldg(rec_x + tid); my_rz = __ldg(rec_z + tid); }
    const bool my_rec = (my_rx >= 0) && ((my_rx >> 2) == bid);
    const int  rec_off = my_rec ? ((4 + (my_rx & 3)) * SROW + 4 + my_rz) : 0;

    // ---- zero SMEM; read own counter base ----
    for (int i = tid; i < SMEM_FLOATS; i += NTHR) sm[i] = 0.0f;
    if (tid == 0) sm_base = g_done[bid * PAD];
    __syncthreads();
    const unsigned long long base = sm_base;

    // ---- register state ----
    const float DT2f = 1.0e-6f;
    float4 m0 = make_float4(0.f,0.f,0.f,0.f), o0 = m0, cf0 = m0;
    float4 m1 = m0, o1 = m0, cf1 = m0;
    {
        const int ga = g0 - 4 + ty;
        if ((unsigned)ga < (unsigned)NX) {
            const float4 v = __ldg(reinterpret_cast<const float4*>(
                                   vel + (size_t)ga * NZ + tx * 4));
            cf0 = make_float4(v.x*v.x*DT2f, v.y*v.y*DT2f, v.z*v.z*DT2f, v.w*v.w*DT2f);
        }
        const int gb = g0 - 4 + ty + 6;
        if ((unsigned)gb < (unsigned)NX) {
            const float4 v = __ldg(reinterpret_cast<const float4*>(
                                   vel + (size_t)gb * NZ + tx * 4));
            cf1 = make_float4(v.x*v.x*DT2f, v.y*v.y*DT2f, v.z*v.z*DT2f, v.w*v.w*DT2f);
        }
    }

    // ---- zero OWN rows of global pair 0 (stale from prior replay) ----
    if (tid < RROWS * 128) {
        const float4 z = make_float4(0.f, 0.f, 0.f, 0.f);
        const int r = tid >> 7, c = tid & 127;
        const size_t off = (size_t)(g0 + r) * NZ + c * 4;
        __stcg(reinterpret_cast<float4*>(g_P[0] + off), z);
        __stcg(reinterpret_cast<float4*>(g_Q[0] + off), z);
    }
    __syncthreads();
    if (tid == 0) signal_done(bid);   // counter -> base+1

    for (int b = 0; b < NBLK; ++b) {
        if (tid == 0)
            wait_neighbors(bid, base + 1 + (unsigned long long)b);
        __syncthreads();

        const int pb = b & 1;
        const float* gp = g_P[pb];
        const float* gq = g_Q[pb];

        // ---- halo refresh: slot0 rows 0..3, slot1 rows 8..11 ----
        if (ty < 4) {   // slot 0, rows 0..3
            const int i = ty;
            const int g = g0 - 4 + i;
            if ((unsigned)g < (unsigned)NX) {
                const float4 v = __ldcg(reinterpret_cast<const float4*>(
                                        gp + (size_t)g * NZ + tx * 4));
                if (i == 3) {
                    o0 = m0;                  // p_{n-1} from prev block's s3
                } else if (i == 1 || i == 2) {
                    o0 = __ldcg(reinterpret_cast<const float4*>(
                                gq + (size_t)g * NZ + tx * 4));
                }
                m0 = v;
                *reinterpret_cast<float4*>(S0 + i * SROW + colbase) = v;
            }
        }
        if (ty >= 2) {  // slot 1, rows 8..11
            const int i = ty + 6;
            const int g = g0 - 4 + i;
            if ((unsigned)g < (unsigned)NX) {
                const float4 v = __ldcg(reinterpret_cast<const float4*>(
                                        gp + (size_t)g * NZ + tx * 4));
                if (i == 8) {
                    o1 = m1;
                } else if (i == 9 || i == 10) {
                    o1 = __ldcg(reinterpret_cast<const float4*>(
                                gq + (size_t)g * NZ + tx * 4));
                }
                m1 = v;
                *reinterpret_cast<float4*>(S0 + i * SROW + colbase) = v;
            }
        }
        __syncthreads();

        const int t0 = b * KST;
        float* gpo = g_P[pb ^ 1];
        float* gqo = g_Q[pb ^ 1];

        // s1: rows [1,10], S0 -> S1
        substep<1, 10, false>(S0, S1, m0, o0, cf0, m1, o1, cf1,
                              clo, chi, g0, tx, ty, sx, sz, source, t0, nullptr);
        __syncthreads();
        if (my_rec) out[(size_t)tid * NSTEPS + t0] = S1[rec_off];

        // s2: rows [2,9], S1 -> S0
        substep<2, 9, false>(S1, S0, m0, o0, cf0, m1, o1, cf1,
                             clo, chi, g0, tx, ty, sx, sz, source, t0 + 1, nullptr);
        __syncthreads();
        if (my_rec) out[(size_t)tid * NSTEPS + t0 + 1] = S0[rec_off];

        // s3: rows [3,8], S0 -> S1; own rows -> Q[pb^1]
        substep<3, 8, true>(S0, S1, m0, o0, cf0, m1, o1, cf1,
                            clo, chi, g0, tx, ty, sx, sz, source, t0 + 2, gqo);
        __syncthreads();
        if (my_rec) out[(size_t)tid * NSTEPS + t0 + 2] = S1[rec_off];

        // s4: rows [4,7], S1 -> S0; own rows -> P[pb^1]
        substep<4, 7, true>(S1, S0, m0, o0, cf0, m1, o1, cf1,
                            clo, chi, g0, tx, ty, sx, sz, source, t0 + 3, gpo);
        __syncthreads();
        if (my_rec) out[(size_t)tid * NSTEPS + t0 + 3] = S0[rec_off];

        if (tid == 0) signal_done(bid);   // counter -> base+2+b
    }
}

extern "C" void kernel_launch(void* const* d_in, const int* in_sizes, int n_in,
                              void* d_out, int out_size)
{
    const float* vel    = (const float*)d_in[0];
    const float* source = (const float*)d_in[1];
    const int*   srcx   = (const int*)d_in[2];
    const int*   srcz   = (const int*)d_in[3];
    const int*   rec_x  = (const int*)d_in[4];
    const int*   rec_z  = (const int*)d_in[5];
    float* out = (float*)d_out;

    cudaFuncSetAttribute(wave_fdtd_reg_kernel,
                         cudaFuncAttributeMaxDynamicSharedMemorySize, SMEM_BYTES);
    wave_fdtd_reg_kernel<<<NCTA, NTHR, SMEM_BYTES>>>(
        vel, source, srcx, srcz, rec_x, rec_z, out);
}